// round 1
// baseline (speedup 1.0000x reference)
#include <cuda_runtime.h>
#include <math.h>

// ---------------- problem constants ----------------
#define MPTS   32768
#define NPTS   (MPTS * 8)          // 262144 upsampled points
#define NV     9
#define NC     24
#define NH     120
#define NW     160
#define CPRE   50
#define CIN    (NC + 1 + CPRE)     // 75
#define CHID   24
#define HW     (NH * NW)
#define VHW    (NV * HW)
#define VOXSZ  0.04f

// ---------------- scratch (device globals; no allocation) ----------------
__device__ __align__(16) float  g_featT[VHW * NC];      // feats transposed to (V,H,W,C)
__device__ __align__(16) float  g_features[NPTS * NC];  // per-point mean features
__device__ float  g_z[NPTS];                            // per-point mean depth
__device__ double g_red[3];                             // sum(z*pos), sum(z^2*pos), sum(pos)

__constant__ int c_off[8][3] = {
    {0,0,0},{1,0,0},{0,1,0},{0,0,1},{1,1,0},{1,0,1},{0,1,1},{1,1,1}
};

// ---------------- kernel 0: zero reduction accumulators ----------------
__global__ void k_zero_red() {
    g_red[0] = 0.0; g_red[1] = 0.0; g_red[2] = 0.0;
}

// ---------------- kernel 1: transpose feats (V,C,H,W) -> (V,H,W,C) ----------------
__global__ void k_transpose(const float* __restrict__ feats) {
    int tid = blockIdx.x * blockDim.x + threadIdx.x;
    if (tid >= VHW) return;
    int v   = tid / HW;
    int rem = tid - v * HW;
    const float* src = feats + (size_t)v * NC * HW + rem;
    float vals[NC];
#pragma unroll
    for (int c = 0; c < NC; c++) vals[c] = src[(size_t)c * HW];   // coalesced across x
    float4* dst = reinterpret_cast<float4*>(g_featT) + (size_t)tid * 6;
#pragma unroll
    for (int j = 0; j < 6; j++)
        dst[j] = make_float4(vals[4*j], vals[4*j+1], vals[4*j+2], vals[4*j+3]);
}

// ---------------- kernel 2: back-projection + per-point stats ----------------
__global__ __launch_bounds__(256) void k_backproject(
    const int*   __restrict__ pre_coords,   // (M,4) int32
    const float* __restrict__ KRcam,        // (V,1,4,4)
    const float* __restrict__ origin,       // (3,)
    const float* __restrict__ w2ac,         // (1,4,4)
    float*       __restrict__ d_out)        // [out 2N | count N | r_coords 4N]
{
    __shared__ float sKR[NV * 16];
    __shared__ float sW2[12];
    __shared__ float sOrg[3];
    int t = threadIdx.x;
    if (t < NV * 16) sKR[t] = KRcam[t];
    if (t < 12)      sW2[t] = w2ac[t];
    if (t < 3)       sOrg[t] = origin[t];
    __syncthreads();

    int n = blockIdx.x * 256 + t;            // grid sized exactly NPTS/256
    int m = n >> 3, k = n & 7;

    int cx = pre_coords[m * 4 + 1] + c_off[k][0];
    int cy = pre_coords[m * 4 + 2] + c_off[k][1];
    int cz = pre_coords[m * 4 + 3] + c_off[k][2];
    float wx = (float)cx * VOXSZ + sOrg[0];
    float wy = (float)cy * VOXSZ + sOrg[1];
    float wz = (float)cz * VOXSZ + sOrg[2];

    // r_coords (independent of views)
    {
        float4 rc;
        rc.x = sW2[0]*wx + sW2[1]*wy + sW2[2]*wz + sW2[3];
        rc.y = sW2[4]*wx + sW2[5]*wy + sW2[6]*wz + sW2[7];
        rc.z = sW2[8]*wx + sW2[9]*wy + sW2[10]*wz + sW2[11];
        rc.w = 0.0f;                          // batch index is always 0
        reinterpret_cast<float4*>(d_out + 3 * NPTS)[n] = rc;
    }

    float4 acc[6];
#pragma unroll
    for (int j = 0; j < 6; j++) acc[j] = make_float4(0.f, 0.f, 0.f, 0.f);
    float zsum = 0.f;
    int   cnt  = 0;

    const float4* base = reinterpret_cast<const float4*>(g_featT);

#pragma unroll 1
    for (int v = 0; v < NV; v++) {
        const float* R = sKR + v * 16;
        float ix = R[0]*wx + R[1]*wy + R[2]*wz  + R[3];
        float iy = R[4]*wx + R[5]*wy + R[6]*wz  + R[7];
        float iz = R[8]*wx + R[9]*wy + R[10]*wz + R[11];
        float sz = (fabsf(iz) > 1e-9f) ? iz : 1e-9f;
        float px = ix / sz;
        float py = iy / sz;
        bool msk = (px >= 0.f) && (px <= (float)(NW - 1)) &&
                   (py >= 0.f) && (py <= (float)(NH - 1)) && (iz > 0.f);
        if (!msk) continue;

        float fx0 = floorf(px), fy0 = floorf(py);
        float ax = px - fx0,    ay = py - fy0;
        int ix0 = (int)fx0,     iy0 = (int)fy0;
        int ix1 = ix0 + 1,      iy1 = iy0 + 1;
        float okx = (ix1 < NW) ? 1.f : 0.f;
        float oky = (iy1 < NH) ? 1.f : 0.f;
        ix1 = min(ix1, NW - 1); iy1 = min(iy1, NH - 1);

        float w00 = (1.f - ax) * (1.f - ay);
        float w10 = ax * (1.f - ay) * okx;
        float w01 = (1.f - ax) * ay * oky;
        float w11 = ax * ay * okx * oky;

        int b00 = ((v * NH + iy0) * NW + ix0) * 6;
        int b10 = ((v * NH + iy0) * NW + ix1) * 6;
        int b01 = ((v * NH + iy1) * NW + ix0) * 6;
        int b11 = ((v * NH + iy1) * NW + ix1) * 6;

#pragma unroll
        for (int j = 0; j < 6; j++) {
            float4 c00 = base[b00 + j];
            float4 c10 = base[b10 + j];
            float4 c01 = base[b01 + j];
            float4 c11 = base[b11 + j];
            acc[j].x += w00*c00.x + w10*c10.x + w01*c01.x + w11*c11.x;
            acc[j].y += w00*c00.y + w10*c10.y + w01*c01.y + w11*c11.y;
            acc[j].z += w00*c00.z + w10*c10.z + w01*c01.z + w11*c11.z;
            acc[j].w += w00*c00.w + w10*c10.w + w01*c01.w + w11*c11.w;
        }
        zsum += iz;
        cnt  += 1;
    }

    float denom = fmaxf((float)cnt, 1.f);
    float inv   = 1.f / denom;
    float4* fdst = reinterpret_cast<float4*>(g_features) + (size_t)n * 6;
#pragma unroll
    for (int j = 0; j < 6; j++) {
        float4 a = acc[j];
        fdst[j] = make_float4(a.x * inv, a.y * inv, a.z * inv, a.w * inv);
    }
    float zv = zsum * inv;
    g_z[n] = zv;
    d_out[2 * NPTS + n] = (float)cnt;

    // global reduction contributions (pos = zv > 0)
    bool  pos = zv > 0.f;
    float r0 = pos ? zv : 0.f;
    float r1 = pos ? zv * zv : 0.f;
    float r2 = pos ? 1.f : 0.f;
#pragma unroll
    for (int o = 16; o > 0; o >>= 1) {
        r0 += __shfl_down_sync(0xffffffffu, r0, o);
        r1 += __shfl_down_sync(0xffffffffu, r1, o);
        r2 += __shfl_down_sync(0xffffffffu, r2, o);
    }
    __shared__ float s0[8], s1[8], s2[8];
    int w = t >> 5, lane = t & 31;
    if (lane == 0) { s0[w] = r0; s1[w] = r1; s2[w] = r2; }
    __syncthreads();
    if (t == 0) {
        float t0 = 0.f, t1 = 0.f, t2 = 0.f;
#pragma unroll
        for (int i = 0; i < 8; i++) { t0 += s0[i]; t1 += s1[i]; t2 += s2[i]; }
        atomicAdd(&g_red[0], (double)t0);
        atomicAdd(&g_red[1], (double)t1);
        atomicAdd(&g_red[2], (double)t2);
    }
}

// ---------------- kernel 3: z-norm + MLP heads ----------------
__device__ __forceinline__ void fma_row(float* h, float fi, const float4* wrow) {
#pragma unroll
    for (int q = 0; q < 6; q++) {
        float4 w = wrow[q];
        h[4*q+0] += fi * w.x;
        h[4*q+1] += fi * w.y;
        h[4*q+2] += fi * w.z;
        h[4*q+3] += fi * w.w;
    }
}

__global__ __launch_bounds__(256) void k_mlp(
    const float* __restrict__ pre_feat,   // (M,50)
    const float* __restrict__ W_sp,       // (75,24)
    const float* __restrict__ b_sp,       // (24,)
    const float* __restrict__ W_t,        // (24,1)
    const float* __restrict__ b_t,        // (1,)
    const float* __restrict__ W_o,        // (24,1)
    const float* __restrict__ b_o,        // (1,)
    float*       __restrict__ d_out)
{
    __shared__ float4 sW[CIN * 6];        // 75 rows x 24 cols
    __shared__ float  sWt[CHID], sWo[CHID], sB[CHID];
    int t = threadIdx.x;
    const float4* Wv = reinterpret_cast<const float4*>(W_sp);
    for (int i = t; i < CIN * 6; i += 256) sW[i] = Wv[i];
    if (t < CHID) { sWt[t] = W_t[t]; sWo[t] = W_o[t]; sB[t] = b_sp[t]; }
    __syncthreads();

    // z normalization constants (redundant per thread, trivial cost)
    double npos  = fmax(g_red[2], 1.0);
    double zmean = g_red[0] / npos;
    double var   = g_red[1] - zmean * zmean * npos;
    float  znorm = (float)sqrt(fmax(var, 0.0)) + 1e-5f;
    float  zmf   = (float)zmean;

    int n = blockIdx.x * 256 + t;

    float h[CHID];
#pragma unroll
    for (int j = 0; j < CHID; j++) h[j] = sB[j];

    // features (24)
    const float4* fsrc = reinterpret_cast<const float4*>(g_features) + (size_t)n * 6;
#pragma unroll
    for (int j4 = 0; j4 < 6; j4++) {
        float4 f = fsrc[j4];
        fma_row(h, f.x, sW + (4*j4 + 0) * 6);
        fma_row(h, f.y, sW + (4*j4 + 1) * 6);
        fma_row(h, f.z, sW + (4*j4 + 2) * 6);
        fma_row(h, f.w, sW + (4*j4 + 3) * 6);
    }
    // zn (1)
    {
        float zv = g_z[n];
        float zn = (zv > 0.f) ? (zv - zmf) / znorm : 0.f;
        fma_row(h, zn, sW + NC * 6);
    }
    // pre_feat (50) — row is 200B: use float2 (8B-aligned for every m)
    {
        const float2* pf = reinterpret_cast<const float2*>(pre_feat + (size_t)(n >> 3) * CPRE);
#pragma unroll
        for (int i = 0; i < CPRE / 2; i++) {
            float2 f = pf[i];
            fma_row(h, f.x, sW + (NC + 1 + 2*i + 0) * 6);
            fma_row(h, f.y, sW + (NC + 1 + 2*i + 1) * 6);
        }
    }

    float tsdf = b_t[0], occ = b_o[0];
#pragma unroll
    for (int j = 0; j < CHID; j++) {
        float hv = fmaxf(h[j], 0.f);
        tsdf += hv * sWt[j];
        occ  += hv * sWo[j];
    }
    reinterpret_cast<float2*>(d_out)[n] = make_float2(tsdf, occ);
}

// ---------------- launch ----------------
extern "C" void kernel_launch(void* const* d_in, const int* in_sizes, int n_in,
                              void* d_out, int out_size)
{
    const float *pre_feat = nullptr, *feats = nullptr, *KRcam = nullptr,
                *origin = nullptr, *w2ac = nullptr, *W_sp = nullptr,
                *b_sp = nullptr, *W_t = nullptr, *b_t = nullptr,
                *W_o = nullptr, *b_o = nullptr;
    const int* pre_coords = nullptr;
    int n24 = 0, n1 = 0;

    for (int i = 0; i < n_in; i++) {
        int s = in_sizes[i];
        const void* p = d_in[i];
        switch (s) {
            case MPTS * CPRE:  pre_feat   = (const float*)p; break;  // 1,638,400
            case MPTS * 4:     pre_coords = (const int*)p;   break;  // 131,072
            case VHW * NC:     feats      = (const float*)p; break;  // 4,147,200
            case NV * 16:      KRcam      = (const float*)p; break;  // 144
            case 3:            origin     = (const float*)p; break;
            case 16:           w2ac       = (const float*)p; break;
            case CIN * CHID:   W_sp       = (const float*)p; break;  // 1800
            case 24:   // in both plausible metadata orders: b_sp, W_t, W_o
                if (n24 == 0) b_sp = (const float*)p;
                else if (n24 == 1) W_t = (const float*)p;
                else W_o = (const float*)p;
                n24++; break;
            case 1:    // b_t then b_o
                if (n1 == 0) b_t = (const float*)p;
                else b_o = (const float*)p;
                n1++; break;
            default: break;
        }
    }

    k_zero_red<<<1, 1>>>();
    k_transpose<<<(VHW + 255) / 256, 256>>>(feats);
    k_backproject<<<NPTS / 256, 256>>>(pre_coords, KRcam, origin, w2ac, (float*)d_out);
    k_mlp<<<NPTS / 256, 256>>>(pre_feat, W_sp, b_sp, W_t, b_t, W_o, b_o, (float*)d_out);
}